// round 14
// baseline (speedup 1.0000x reference)
#include <cuda_runtime.h>
#include <cuda_fp16.h>
#include <cstdint>
#include <math.h>

// Problem constants
constexpr int Bz = 4;
constexpr int Sq = 2048;
constexpr int Dm = 1024;
constexpr int Hh = 16;
constexpr int Dh = 64;
constexpr int Mr = Bz * Sq;    // 8192

// Scratch (allocation-free rule: __device__ globals)
__device__ __half g_xh[(size_t)Mr * Dm];      // x fp16; later reused for attn-out
__device__ __half g_w[4][(size_t)Dm * Dm];    // Wq, Wk, Wv, Wo fp16 (contiguous)
__device__ __half g_Qh[(size_t)Mr * Dm];
__device__ __half g_Kh[(size_t)Mr * Dm];
__device__ __half g_Vh[(size_t)Mr * Dm];

// ===========================================================================
// PTX helpers
// ===========================================================================
__device__ __forceinline__ uint32_t smem_to_u32(const void* p) {
    uint32_t a;
    asm("{ .reg .u64 t; cvta.to.shared.u64 t, %1; cvt.u32.u64 %0, t; }"
        : "=r"(a) : "l"(p));
    return a;
}
__device__ __forceinline__ void cp16(uint32_t dst, const void* src) {
    asm volatile("cp.async.cg.shared.global [%0], [%1], 16;" :: "r"(dst), "l"(src));
}
#define CP_COMMIT() asm volatile("cp.async.commit_group;" ::: "memory")
#define CP_WAIT1()  asm volatile("cp.async.wait_group 1;" ::: "memory")
#define CP_WAIT0()  asm volatile("cp.async.wait_group 0;" ::: "memory")

__device__ __forceinline__ void ldsm4(uint32_t* r, uint32_t addr) {
    asm volatile("ldmatrix.sync.aligned.m8n8.x4.shared.b16 {%0,%1,%2,%3}, [%4];"
        : "=r"(r[0]), "=r"(r[1]), "=r"(r[2]), "=r"(r[3]) : "r"(addr));
}
__device__ __forceinline__ void ldsm4t(uint32_t* r, uint32_t addr) {
    asm volatile("ldmatrix.sync.aligned.m8n8.x4.trans.shared.b16 {%0,%1,%2,%3}, [%4];"
        : "=r"(r[0]), "=r"(r[1]), "=r"(r[2]), "=r"(r[3]) : "r"(addr));
}
__device__ __forceinline__ void mma_f16(float* d, const uint32_t* a,
                                        uint32_t b0, uint32_t b1) {
    asm volatile(
        "mma.sync.aligned.m16n8k16.row.col.f32.f16.f16.f32 "
        "{%0,%1,%2,%3}, {%4,%5,%6,%7}, {%8,%9}, {%0,%1,%2,%3};"
        : "+f"(d[0]), "+f"(d[1]), "+f"(d[2]), "+f"(d[3])
        : "r"(a[0]), "r"(a[1]), "r"(a[2]), "r"(a[3]), "r"(b0), "r"(b1));
}
__device__ __forceinline__ uint32_t ex2_h2(uint32_t x) {
    uint32_t r;
    asm("ex2.approx.f16x2 %0, %1;" : "=r"(r) : "r"(x));
    return r;
}

// ===========================================================================
// Conversion: single launch, blockIdx.y selects tensor (0=x, 1..4=weights)
// ===========================================================================
__global__ __launch_bounds__(256)
void cvt_all(const float* __restrict__ x,
             const float* __restrict__ w0, const float* __restrict__ w1,
             const float* __restrict__ w2, const float* __restrict__ w3,
             __half* __restrict__ xh, __half* __restrict__ wdst,
             int xn4, int wn4)
{
    const int sel = blockIdx.y;
    const float* src;
    __half* dst;
    int n4;
    if (sel == 0)      { src = x;  dst = xh;                          n4 = xn4; }
    else if (sel == 1) { src = w0; dst = wdst + 0 * (size_t)wn4 * 4;  n4 = wn4; }
    else if (sel == 2) { src = w1; dst = wdst + 1 * (size_t)wn4 * 4;  n4 = wn4; }
    else if (sel == 3) { src = w2; dst = wdst + 2 * (size_t)wn4 * 4;  n4 = wn4; }
    else               { src = w3; dst = wdst + 3 * (size_t)wn4 * 4;  n4 = wn4; }

    int i = blockIdx.x * blockDim.x + threadIdx.x;
    if (i >= n4) return;
    float4 v = reinterpret_cast<const float4*>(src)[i];
    reinterpret_cast<__half2*>(dst)[2 * i + 0] = __floats2half2_rn(v.x, v.y);
    reinterpret_cast<__half2*>(dst)[2 * i + 1] = __floats2half2_rn(v.z, v.w);
}

// ===========================================================================
// GEMM: 128x128 tiles, k-chunk 64, 8 warps, 3-stage cp.async ring
// ===========================================================================
constexpr int TBM = 128, TBN = 128, TKC = 64;
constexpr int ROWB  = 144;           // 64 fp16 = 128B + 16B pad
constexpr int TILEB = 128 * ROWB;    // 18432
constexpr int GSTG  = 2 * TILEB;     // A+B per stage = 36864
constexpr int GSMEM = 3 * GSTG;      // 110592 (2 CTA/SM: 221KB < 228KB)

__device__ __forceinline__ void gemm_issue(
    const __half* A, const __half* B,
    uint32_t sb, int tid, int bm, int bn, int k0, int stage)
{
    #pragma unroll
    for (int i = 0; i < 8; i++) {
        int idx = tid + i * 256;          // 0..2047
        int tile = idx >> 10;             // 0=A 1=B
        int row  = (idx >> 3) & 127;
        int c16  = idx & 7;
        const __half* src = tile ? B : A;
        int grow = (tile ? bn : bm) + row;
        const char* gsrc = reinterpret_cast<const char*>(src + (size_t)grow * Dm + k0)
                           + c16 * 16;
        uint32_t dst = sb + stage * GSTG + tile * TILEB + row * ROWB + c16 * 16;
        cp16(dst, gsrc);
    }
    CP_COMMIT();
}

__device__ __forceinline__ void gemm_mainloop(
    const __half* A, const __half* B, uint32_t sb, int tid,
    int bm, int bn, int wr, int wc, int lane, float acc[2][8][4])
{
    const uint32_t aOff = (lane % 16) * ROWB + (lane / 16) * 16;
    const uint32_t bOff = (((lane >> 4) << 3) + (lane & 7)) * ROWB + ((lane >> 3) & 1) * 16;

    gemm_issue(A, B, sb, tid, bm, bn, 0, 0);
    gemm_issue(A, B, sb, tid, bm, bn, TKC, 1);

    const int NCK = Dm / TKC;    // 16
    int stage = 0;
    for (int ck = 0; ck < NCK; ck++) {
        if (ck + 1 < NCK) { CP_WAIT1(); } else { CP_WAIT0(); }
        __syncthreads();
        if (ck + 2 < NCK) {
            int st2 = stage + 2; if (st2 >= 3) st2 -= 3;
            gemm_issue(A, B, sb, tid, bm, bn, (ck + 2) * TKC, st2);
        }

        const uint32_t stg = sb + stage * GSTG;
        const uint32_t aB  = stg + (wr * 32) * ROWB + aOff;
        const uint32_t bB  = stg + TILEB + (wc * 64) * ROWB + bOff;

        #pragma unroll
        for (int ks = 0; ks < 4; ks++) {
            uint32_t ah[2][4];
            #pragma unroll
            for (int mt = 0; mt < 2; mt++)
                ldsm4(ah[mt], aB + mt * 16 * ROWB + ks * 32);
            #pragma unroll
            for (int nt = 0; nt < 4; nt++) {
                uint32_t bh[4];
                ldsm4(bh, bB + nt * 16 * ROWB + ks * 32);
                #pragma unroll
                for (int mt = 0; mt < 2; mt++) {
                    mma_f16(acc[mt][2 * nt + 0], ah[mt], bh[0], bh[1]);
                    mma_f16(acc[mt][2 * nt + 1], ah[mt], bh[2], bh[3]);
                }
            }
        }
        if (++stage == 3) stage = 0;
    }
}

// ---------------------------------------------------------------------------
// Fused QKV projection: B = packed [Wq;Wk;Wv]. fp16 scatter.
// Q outputs pre-scaled by (1/sqrt(Dh))*log2(e) for the flash exp2 domain.
// ---------------------------------------------------------------------------
constexpr float QSCALE = 0.18033688011112042f;  // (1/8) * log2(e)

__global__ __launch_bounds__(256, 2)
void gemm_qkv(const __half* __restrict__ A, const __half* __restrict__ Bw,
              const float* __restrict__ bq, const float* __restrict__ bk,
              const float* __restrict__ bv,
              __half* __restrict__ Qh, __half* __restrict__ Kh,
              __half* __restrict__ Vh)
{
    extern __shared__ char smem[];
    const uint32_t sb = smem_to_u32(smem);
    const int tid = threadIdx.x;
    const int wid = tid >> 5, lane = tid & 31;
    const int bm = blockIdx.y * TBM, bn = blockIdx.x * TBN;   // bn in [0,3072)
    const int wr = wid & 3, wc = wid >> 2;

    float acc[2][8][4];
    #pragma unroll
    for (int a = 0; a < 2; a++)
        #pragma unroll
        for (int b = 0; b < 8; b++)
            #pragma unroll
            for (int c = 0; c < 4; c++) acc[a][b][c] = 0.f;

    gemm_mainloop(A, Bw, sb, tid, bm, bn, wr, wc, lane, acc);

    const int sel = bn >> 10;
    const int bnl = bn & 1023;
    const float* bias = (sel == 0) ? bq : (sel == 1) ? bk : bv;
    __half* dst = (sel == 0) ? Qh : (sel == 1) ? Kh : Vh;
    const float osc = (sel == 0) ? QSCALE : 1.0f;

    const int grp = lane >> 2, qid = lane & 3;
    #pragma unroll
    for (int mt = 0; mt < 2; mt++) {
        #pragma unroll
        for (int na = 0; na < 8; na++) {
            const int n0 = bnl + wc * 64 + na * 8 + qid * 2;
            const float b0 = bias[n0], b1 = bias[n0 + 1];
            #pragma unroll
            for (int half = 0; half < 2; half++) {
                const int m = bm + wr * 32 + mt * 16 + grp + half * 8;
                const float v0 = (acc[mt][na][2 * half + 0] + b0) * osc;
                const float v1 = (acc[mt][na][2 * half + 1] + b1) * osc;
                const int b = m >> 11;
                const int sI = m & 2047;
                const int h = n0 >> 6;
                const int d = n0 & 63;
                const size_t o = ((((size_t)b * Hh + h) * Sq + sI) << 6) + d;
                *reinterpret_cast<__half2*>(&dst[o]) = __floats2half2_rn(v0, v1);
            }
        }
    }
}

// ---------------------------------------------------------------------------
// Output projection: fp32 row-major out
// ---------------------------------------------------------------------------
__global__ __launch_bounds__(256, 2)
void gemm_out(const __half* __restrict__ A, const __half* __restrict__ Bw,
              const float* __restrict__ bias, float* __restrict__ C)
{
    extern __shared__ char smem[];
    const uint32_t sb = smem_to_u32(smem);
    const int tid = threadIdx.x;
    const int wid = tid >> 5, lane = tid & 31;
    const int bm = blockIdx.y * TBM, bn = blockIdx.x * TBN;
    const int wr = wid & 3, wc = wid >> 2;

    float acc[2][8][4];
    #pragma unroll
    for (int a = 0; a < 2; a++)
        #pragma unroll
        for (int b = 0; b < 8; b++)
            #pragma unroll
            for (int c = 0; c < 4; c++) acc[a][b][c] = 0.f;

    gemm_mainloop(A, Bw, sb, tid, bm, bn, wr, wc, lane, acc);

    const int grp = lane >> 2, qid = lane & 3;
    #pragma unroll
    for (int mt = 0; mt < 2; mt++) {
        #pragma unroll
        for (int na = 0; na < 8; na++) {
            const int n0 = bn + wc * 64 + na * 8 + qid * 2;
            const float b0 = bias[n0], b1 = bias[n0 + 1];
            #pragma unroll
            for (int half = 0; half < 2; half++) {
                const int m = bm + wr * 32 + mt * 16 + grp + half * 8;
                *reinterpret_cast<float2*>(&C[(size_t)m * Dm + n0]) =
                    make_float2(acc[mt][na][2 * half + 0] + b0,
                                acc[mt][na][2 * half + 1] + b1);
            }
        }
    }
}

// ===========================================================================
// Tensor-core flash attention (R13 config — best measured).
// FBQ=128, 8 warps, 2 CTA/SM, 128-key chunks (2 subtiles per sync),
// 2-stage ring, f16x2 exp, row sums via MMA-with-ones, Q pre-scaled.
// Output fp16 row-major [b*s, Dm].
// ===========================================================================
constexpr int FBQ = 128, FBK = 64, FCH = 128;
constexpr int FROWB = 144;
constexpr int F_Q   = 0;
constexpr int F_KV  = FBQ * FROWB;
constexpr int KVSTG = 2 * FCH * FROWB;          // 36864
constexpr int FSMEM = F_KV + 2 * KVSTG;         // 92160

__global__ __launch_bounds__(256, 2)
void flash_tc(const __half* __restrict__ Qh, const __half* __restrict__ Kh,
              const __half* __restrict__ Vh, __half* __restrict__ Oh)
{
    extern __shared__ char smem[];
    const uint32_t sb = smem_to_u32(smem);
    const int tid = threadIdx.x;
    const int w = tid >> 5, lane = tid & 31;
    const int grp = lane >> 2, qid = lane & 3;

    const int bh = blockIdx.y;
    const int qt = gridDim.x - 1 - blockIdx.x;   // big tiles first
    const int q0 = qt * FBQ;
    const size_t rowbase = (size_t)bh * Sq;

    constexpr uint32_t ONE2 = 0x3C003C00;

    #pragma unroll
    for (int i = 0; i < 4; i++) {
        int idx = tid + i * 256;
        int row = idx >> 3;
        int c = idx & 7;
        cp16(sb + F_Q + row * FROWB + c * 16,
             reinterpret_cast<const char*>(Qh + (rowbase + q0 + row) * Dh) + c * 16);
    }
    CP_COMMIT();

    auto issue_kv = [&](int k0, int stg) {
        const uint32_t base = sb + F_KV + stg * KVSTG;
        #pragma unroll
        for (int i = 0; i < 8; i++) {
            int idx = tid + i * 256;
            int arr = idx >> 10;               // 0=K 1=V
            int row = (idx >> 3) & 127;
            int c = idx & 7;
            const char* src = arr
                ? (const char*)(Vh + (rowbase + k0 + row) * Dh)
                : (const char*)(Kh + (rowbase + k0 + row) * Dh);
            cp16(base + arr * (FCH * FROWB) + row * FROWB + c * 16, src + c * 16);
        }
        CP_COMMIT();
    };

    const int NCH = qt + 1;
    issue_kv(0, 0);

    float m0 = -1e30f, m1 = -1e30f;
    float o[8][4], ls[4];
    #pragma unroll
    for (int t = 0; t < 8; t++)
        #pragma unroll
        for (int i = 0; i < 4; i++) o[t][i] = 0.f;
    #pragma unroll
    for (int i = 0; i < 4; i++) ls[i] = 0.f;

    const int rw0 = q0 + w * 16;
    const uint32_t aOffQ = sb + F_Q + (w * 16 + lane % 16) * FROWB + (lane / 16) * 16;
    const uint32_t bOffK = (((lane >> 4) << 3) + (lane & 7)) * FROWB + ((lane >> 3) & 1) * 16;

    int s = 0;
    for (int ch = 0; ch < NCH; ch++) {
        CP_WAIT0();
        __syncthreads();
        if (ch + 1 < NCH) issue_kv((ch + 1) * FCH, s ^ 1);

        const uint32_t chbase = sb + F_KV + s * KVSTG;

        #pragma unroll
        for (int sub = 0; sub < 2; sub++) {
            const int k0 = ch * FCH + sub * FBK;
            if (k0 > rw0 + 15) continue;

            const uint32_t kbase = chbase + sub * (FBK * FROWB);
            const uint32_t vbase = chbase + FCH * FROWB + sub * (FBK * FROWB);

            float sc[8][4];
            #pragma unroll
            for (int t = 0; t < 8; t++)
                #pragma unroll
                for (int i = 0; i < 4; i++) sc[t][i] = 0.f;

            #pragma unroll
            for (int ks = 0; ks < 4; ks++) {
                uint32_t ah[4];
                ldsm4(ah, aOffQ + ks * 32);
                #pragma unroll
                for (int ntp = 0; ntp < 4; ntp++) {
                    uint32_t bhr[4];
                    ldsm4(bhr, kbase + ntp * 16 * FROWB + bOffK + ks * 32);
                    mma_f16(sc[2 * ntp + 0], ah, bhr[0], bhr[1]);
                    mma_f16(sc[2 * ntp + 1], ah, bhr[2], bhr[3]);
                }
            }

            const bool needMask = (k0 + FBK - 1 > rw0);
            const int r0g = rw0 + grp, r1g = r0g + 8;
            if (needMask) {
                #pragma unroll
                for (int t = 0; t < 8; t++) {
                    const int jc = k0 + t * 8 + qid * 2;
                    if (jc + 0 > r0g) sc[t][0] = -1e4f;
                    if (jc + 1 > r0g) sc[t][1] = -1e4f;
                    if (jc + 0 > r1g) sc[t][2] = -1e4f;
                    if (jc + 1 > r1g) sc[t][3] = -1e4f;
                }
            }

            float mx0 = sc[0][0], mx1 = sc[0][2];
            #pragma unroll
            for (int t = 0; t < 8; t++) {
                mx0 = fmaxf(mx0, fmaxf(sc[t][0], sc[t][1]));
                mx1 = fmaxf(mx1, fmaxf(sc[t][2], sc[t][3]));
            }
            mx0 = fmaxf(mx0, __shfl_xor_sync(0xffffffff, mx0, 1));
            mx0 = fmaxf(mx0, __shfl_xor_sync(0xffffffff, mx0, 2));
            mx1 = fmaxf(mx1, __shfl_xor_sync(0xffffffff, mx1, 1));
            mx1 = fmaxf(mx1, __shfl_xor_sync(0xffffffff, mx1, 2));
            const float nm0 = fmaxf(m0, mx0), nm1 = fmaxf(m1, mx1);
            const float f0 = exp2f(m0 - nm0), f1 = exp2f(m1 - nm1);
            m0 = nm0; m1 = nm1;

            uint32_t pp[8][2];
            #pragma unroll
            for (int t = 0; t < 8; t++) {
                __half2 h01 = __floats2half2_rn(sc[t][0] - nm0, sc[t][1] - nm0);
                __half2 h23 = __floats2half2_rn(sc[t][2] - nm1, sc[t][3] - nm1);
                pp[t][0] = ex2_h2(*reinterpret_cast<uint32_t*>(&h01));
                pp[t][1] = ex2_h2(*reinterpret_cast<uint32_t*>(&h23));
            }

            #pragma unroll
            for (int t = 0; t < 8; t++) {
                o[t][0] *= f0; o[t][1] *= f0; o[t][2] *= f1; o[t][3] *= f1;
            }
            ls[0] *= f0; ls[1] *= f0; ls[2] *= f1; ls[3] *= f1;

            #pragma unroll
            for (int kk = 0; kk < 4; kk++) {
                uint32_t a[4] = { pp[2 * kk][0], pp[2 * kk][1],
                                  pp[2 * kk + 1][0], pp[2 * kk + 1][1] };
                mma_f16(ls, a, ONE2, ONE2);
                #pragma unroll
                for (int ntp = 0; ntp < 4; ntp++) {
                    uint32_t bv[4];
                    ldsm4t(bv, vbase + (kk * 16 + (lane & 15)) * FROWB
                               + (2 * ntp + (lane >> 4)) * 16);
                    mma_f16(o[2 * ntp + 0], a, bv[0], bv[1]);
                    mma_f16(o[2 * ntp + 1], a, bv[2], bv[3]);
                }
            }
        }
        s ^= 1;
    }

    const int b = bh >> 4, h = bh & 15;
    const float inv0 = 1.0f / ls[0], inv1 = 1.0f / ls[2];
    const size_t row0 = ((size_t)b * Sq + (q0 + w * 16 + grp)) * Dm + h * Dh;
    const size_t row1 = row0 + 8 * Dm;
    #pragma unroll
    for (int t = 0; t < 8; t++) {
        const int col = t * 8 + qid * 2;
        *reinterpret_cast<__half2*>(&Oh[row0 + col]) =
            __floats2half2_rn(o[t][0] * inv0, o[t][1] * inv0);
        *reinterpret_cast<__half2*>(&Oh[row1 + col]) =
            __floats2half2_rn(o[t][2] * inv1, o[t][3] * inv1);
    }
}

// ===========================================================================
extern "C" void kernel_launch(void* const* d_in, const int* in_sizes, int n_in,
                              void* d_out, int out_size)
{
    const float* x  = (const float*)d_in[0];
    const float* Wq = (const float*)d_in[2];
    const float* bq = (const float*)d_in[3];
    const float* Wk = (const float*)d_in[4];
    const float* bk = (const float*)d_in[5];
    const float* Wv = (const float*)d_in[6];
    const float* bv = (const float*)d_in[7];
    const float* Wo = (const float*)d_in[8];
    const float* bo = (const float*)d_in[9];
    float* out = (float*)d_out;

    __half *xh, *wptr, *qh, *kh, *vh;
    cudaGetSymbolAddress((void**)&xh, g_xh);
    cudaGetSymbolAddress((void**)&wptr, g_w);
    cudaGetSymbolAddress((void**)&qh, g_Qh);
    cudaGetSymbolAddress((void**)&kh, g_Kh);
    cudaGetSymbolAddress((void**)&vh, g_Vh);

    static bool attr_set = false;
    if (!attr_set) {
        cudaFuncSetAttribute(gemm_qkv, cudaFuncAttributeMaxDynamicSharedMemorySize, GSMEM);
        cudaFuncSetAttribute(gemm_out, cudaFuncAttributeMaxDynamicSharedMemorySize, GSMEM);
        cudaFuncSetAttribute(flash_tc, cudaFuncAttributeMaxDynamicSharedMemorySize, FSMEM);
        attr_set = true;
    }

    const int xn4 = Mr * Dm / 4;                 // 2M float4
    const int wn4 = Dm * Dm / 4;                 // 256K float4
    const size_t wN = (size_t)Dm * Dm;

    // single conversion launch: y=0 -> x, y=1..4 -> weights
    cvt_all<<<dim3((xn4 + 255) / 256, 5), 256>>>(x, Wq, Wk, Wv, Wo, xh, wptr,
                                                 xn4, wn4);

    gemm_qkv<<<dim3(3 * Dm / TBN, Mr / TBM), 256, GSMEM>>>(
        xh, wptr, bq, bk, bv, qh, kh, vh);

    flash_tc<<<dim3(Sq / FBQ, Bz * Hh), 256, FSMEM>>>(qh, kh, vh, xh);

    gemm_out<<<dim3(Dm / TBN, Mr / TBM), 256, GSMEM>>>(xh, wptr + 3 * wN, bo, out);
}

// round 15
// speedup vs baseline: 1.0235x; 1.0235x over previous
#include <cuda_runtime.h>
#include <cuda_fp16.h>
#include <cstdint>
#include <math.h>

// Problem constants
constexpr int Bz = 4;
constexpr int Sq = 2048;
constexpr int Dm = 1024;
constexpr int Hh = 16;
constexpr int Dh = 64;
constexpr int Mr = Bz * Sq;    // 8192

// Scratch (allocation-free rule: __device__ globals)
__device__ __half g_xh[(size_t)Mr * Dm];      // x fp16; later reused for attn-out
__device__ __half g_w[4][(size_t)Dm * Dm];    // Wq, Wk, Wv, Wo fp16 (contiguous)
__device__ __half g_Qh[(size_t)Mr * Dm];
__device__ __half g_Kh[(size_t)Mr * Dm];
__device__ __half g_Vh[(size_t)Mr * Dm];

// ===========================================================================
// PTX helpers
// ===========================================================================
__device__ __forceinline__ uint32_t smem_to_u32(const void* p) {
    uint32_t a;
    asm("{ .reg .u64 t; cvta.to.shared.u64 t, %1; cvt.u32.u64 %0, t; }"
        : "=r"(a) : "l"(p));
    return a;
}
__device__ __forceinline__ void cp16(uint32_t dst, const void* src) {
    asm volatile("cp.async.cg.shared.global [%0], [%1], 16;" :: "r"(dst), "l"(src));
}
#define CP_COMMIT() asm volatile("cp.async.commit_group;" ::: "memory")
#define CP_WAIT1()  asm volatile("cp.async.wait_group 1;" ::: "memory")
#define CP_WAIT0()  asm volatile("cp.async.wait_group 0;" ::: "memory")

__device__ __forceinline__ void ldsm4(uint32_t* r, uint32_t addr) {
    asm volatile("ldmatrix.sync.aligned.m8n8.x4.shared.b16 {%0,%1,%2,%3}, [%4];"
        : "=r"(r[0]), "=r"(r[1]), "=r"(r[2]), "=r"(r[3]) : "r"(addr));
}
__device__ __forceinline__ void ldsm4t(uint32_t* r, uint32_t addr) {
    asm volatile("ldmatrix.sync.aligned.m8n8.x4.trans.shared.b16 {%0,%1,%2,%3}, [%4];"
        : "=r"(r[0]), "=r"(r[1]), "=r"(r[2]), "=r"(r[3]) : "r"(addr));
}
__device__ __forceinline__ void mma_f16(float* d, const uint32_t* a,
                                        uint32_t b0, uint32_t b1) {
    asm volatile(
        "mma.sync.aligned.m16n8k16.row.col.f32.f16.f16.f32 "
        "{%0,%1,%2,%3}, {%4,%5,%6,%7}, {%8,%9}, {%0,%1,%2,%3};"
        : "+f"(d[0]), "+f"(d[1]), "+f"(d[2]), "+f"(d[3])
        : "r"(a[0]), "r"(a[1]), "r"(a[2]), "r"(a[3]), "r"(b0), "r"(b1));
}
__device__ __forceinline__ uint32_t ex2_h2(uint32_t x) {
    uint32_t r;
    asm("ex2.approx.f16x2 %0, %1;" : "=r"(r) : "r"(x));
    return r;
}

// ===========================================================================
// Conversion: single launch, blockIdx.y selects tensor (0=x, 1..4=weights)
// ===========================================================================
__global__ __launch_bounds__(256)
void cvt_all(const float* __restrict__ x,
             const float* __restrict__ w0, const float* __restrict__ w1,
             const float* __restrict__ w2, const float* __restrict__ w3,
             __half* __restrict__ xh, __half* __restrict__ wdst,
             int xn4, int wn4)
{
    const int sel = blockIdx.y;
    const float* src;
    __half* dst;
    int n4;
    if (sel == 0)      { src = x;  dst = xh;                          n4 = xn4; }
    else if (sel == 1) { src = w0; dst = wdst + 0 * (size_t)wn4 * 4;  n4 = wn4; }
    else if (sel == 2) { src = w1; dst = wdst + 1 * (size_t)wn4 * 4;  n4 = wn4; }
    else if (sel == 3) { src = w2; dst = wdst + 2 * (size_t)wn4 * 4;  n4 = wn4; }
    else               { src = w3; dst = wdst + 3 * (size_t)wn4 * 4;  n4 = wn4; }

    int i = blockIdx.x * blockDim.x + threadIdx.x;
    if (i >= n4) return;
    float4 v = reinterpret_cast<const float4*>(src)[i];
    reinterpret_cast<__half2*>(dst)[2 * i + 0] = __floats2half2_rn(v.x, v.y);
    reinterpret_cast<__half2*>(dst)[2 * i + 1] = __floats2half2_rn(v.z, v.w);
}

// ===========================================================================
// GEMM: 128x128 tiles, k-chunk 64, 8 warps, 2-stage cp.async ring (R13 config)
// ===========================================================================
constexpr int TBM = 128, TBN = 128, TKC = 64;
constexpr int ROWB  = 144;           // 64 fp16 = 128B + 16B pad
constexpr int TILEB = 128 * ROWB;    // 18432
constexpr int GSTG  = 2 * TILEB;     // A+B per stage = 36864
constexpr int GSMEM = 2 * GSTG;      // 73728

__device__ __forceinline__ void gemm_issue(
    const __half* A, const __half* B,
    uint32_t sb, int tid, int bm, int bn, int k0, int stage)
{
    #pragma unroll
    for (int i = 0; i < 8; i++) {
        int idx = tid + i * 256;          // 0..2047
        int tile = idx >> 10;             // 0=A 1=B
        int row  = (idx >> 3) & 127;
        int c16  = idx & 7;
        const __half* src = tile ? B : A;
        int grow = (tile ? bn : bm) + row;
        const char* gsrc = reinterpret_cast<const char*>(src + (size_t)grow * Dm + k0)
                           + c16 * 16;
        uint32_t dst = sb + stage * GSTG + tile * TILEB + row * ROWB + c16 * 16;
        cp16(dst, gsrc);
    }
    CP_COMMIT();
}

__device__ __forceinline__ void gemm_mainloop(
    const __half* A, const __half* B, uint32_t sb, int tid,
    int bm, int bn, int wr, int wc, int lane, float acc[2][8][4])
{
    const uint32_t aOff = (lane % 16) * ROWB + (lane / 16) * 16;
    const uint32_t bOff = (((lane >> 4) << 3) + (lane & 7)) * ROWB + ((lane >> 3) & 1) * 16;

    gemm_issue(A, B, sb, tid, bm, bn, 0, 0);

    const int NCK = Dm / TKC;    // 16
    int s = 0;
    for (int ck = 0; ck < NCK; ck++) {
        CP_WAIT0();
        __syncthreads();
        if (ck + 1 < NCK)
            gemm_issue(A, B, sb, tid, bm, bn, (ck + 1) * TKC, s ^ 1);

        const uint32_t stg = sb + s * GSTG;
        const uint32_t aB  = stg + (wr * 32) * ROWB + aOff;
        const uint32_t bB  = stg + TILEB + (wc * 64) * ROWB + bOff;

        #pragma unroll
        for (int ks = 0; ks < 4; ks++) {
            uint32_t ah[2][4];
            #pragma unroll
            for (int mt = 0; mt < 2; mt++)
                ldsm4(ah[mt], aB + mt * 16 * ROWB + ks * 32);
            #pragma unroll
            for (int nt = 0; nt < 4; nt++) {
                uint32_t bh[4];
                ldsm4(bh, bB + nt * 16 * ROWB + ks * 32);
                #pragma unroll
                for (int mt = 0; mt < 2; mt++) {
                    mma_f16(acc[mt][2 * nt + 0], ah[mt], bh[0], bh[1]);
                    mma_f16(acc[mt][2 * nt + 1], ah[mt], bh[2], bh[3]);
                }
            }
        }
        s ^= 1;
    }
}

// ---------------------------------------------------------------------------
// Fused QKV projection: B = packed [Wq;Wk;Wv]. fp16 scatter.
// Q outputs pre-scaled by (1/sqrt(Dh))*log2(e) for the flash exp2 domain.
// ---------------------------------------------------------------------------
constexpr float QSCALE = 0.18033688011112042f;  // (1/8) * log2(e)

__global__ __launch_bounds__(256, 2)
void gemm_qkv(const __half* __restrict__ A, const __half* __restrict__ Bw,
              const float* __restrict__ bq, const float* __restrict__ bk,
              const float* __restrict__ bv,
              __half* __restrict__ Qh, __half* __restrict__ Kh,
              __half* __restrict__ Vh)
{
    extern __shared__ char smem[];
    const uint32_t sb = smem_to_u32(smem);
    const int tid = threadIdx.x;
    const int wid = tid >> 5, lane = tid & 31;
    const int bm = blockIdx.y * TBM, bn = blockIdx.x * TBN;   // bn in [0,3072)
    const int wr = wid & 3, wc = wid >> 2;

    float acc[2][8][4];
    #pragma unroll
    for (int a = 0; a < 2; a++)
        #pragma unroll
        for (int b = 0; b < 8; b++)
            #pragma unroll
            for (int c = 0; c < 4; c++) acc[a][b][c] = 0.f;

    gemm_mainloop(A, Bw, sb, tid, bm, bn, wr, wc, lane, acc);

    const int sel = bn >> 10;
    const int bnl = bn & 1023;
    const float* bias = (sel == 0) ? bq : (sel == 1) ? bk : bv;
    __half* dst = (sel == 0) ? Qh : (sel == 1) ? Kh : Vh;
    const float osc = (sel == 0) ? QSCALE : 1.0f;

    const int grp = lane >> 2, qid = lane & 3;
    #pragma unroll
    for (int mt = 0; mt < 2; mt++) {
        #pragma unroll
        for (int na = 0; na < 8; na++) {
            const int n0 = bnl + wc * 64 + na * 8 + qid * 2;
            const float b0 = bias[n0], b1 = bias[n0 + 1];
            #pragma unroll
            for (int half = 0; half < 2; half++) {
                const int m = bm + wr * 32 + mt * 16 + grp + half * 8;
                const float v0 = (acc[mt][na][2 * half + 0] + b0) * osc;
                const float v1 = (acc[mt][na][2 * half + 1] + b1) * osc;
                const int b = m >> 11;
                const int sI = m & 2047;
                const int h = n0 >> 6;
                const int d = n0 & 63;
                const size_t o = ((((size_t)b * Hh + h) * Sq + sI) << 6) + d;
                *reinterpret_cast<__half2*>(&dst[o]) = __floats2half2_rn(v0, v1);
            }
        }
    }
}

// ---------------------------------------------------------------------------
// Output projection: fp32 row-major out
// ---------------------------------------------------------------------------
__global__ __launch_bounds__(256, 2)
void gemm_out(const __half* __restrict__ A, const __half* __restrict__ Bw,
              const float* __restrict__ bias, float* __restrict__ C)
{
    extern __shared__ char smem[];
    const uint32_t sb = smem_to_u32(smem);
    const int tid = threadIdx.x;
    const int wid = tid >> 5, lane = tid & 31;
    const int bm = blockIdx.y * TBM, bn = blockIdx.x * TBN;
    const int wr = wid & 3, wc = wid >> 2;

    float acc[2][8][4];
    #pragma unroll
    for (int a = 0; a < 2; a++)
        #pragma unroll
        for (int b = 0; b < 8; b++)
            #pragma unroll
            for (int c = 0; c < 4; c++) acc[a][b][c] = 0.f;

    gemm_mainloop(A, Bw, sb, tid, bm, bn, wr, wc, lane, acc);

    const int grp = lane >> 2, qid = lane & 3;
    #pragma unroll
    for (int mt = 0; mt < 2; mt++) {
        #pragma unroll
        for (int na = 0; na < 8; na++) {
            const int n0 = bn + wc * 64 + na * 8 + qid * 2;
            const float b0 = bias[n0], b1 = bias[n0 + 1];
            #pragma unroll
            for (int half = 0; half < 2; half++) {
                const int m = bm + wr * 32 + mt * 16 + grp + half * 8;
                *reinterpret_cast<float2*>(&C[(size_t)m * Dm + n0]) =
                    make_float2(acc[mt][na][2 * half + 0] + b0,
                                acc[mt][na][2 * half + 1] + b1);
            }
        }
    }
}

// ===========================================================================
// Tensor-core flash attention (R13 config — best measured).
// FBQ=128, 8 warps, 2 CTA/SM, 128-key chunks (2 subtiles per sync),
// 2-stage ring, f16x2 exp, row sums via MMA-with-ones, Q pre-scaled.
// Output fp16 row-major [b*s, Dm].
// ===========================================================================
constexpr int FBQ = 128, FBK = 64, FCH = 128;
constexpr int FROWB = 144;
constexpr int F_Q   = 0;
constexpr int F_KV  = FBQ * FROWB;
constexpr int KVSTG = 2 * FCH * FROWB;          // 36864
constexpr int FSMEM = F_KV + 2 * KVSTG;         // 92160

__global__ __launch_bounds__(256, 2)
void flash_tc(const __half* __restrict__ Qh, const __half* __restrict__ Kh,
              const __half* __restrict__ Vh, __half* __restrict__ Oh)
{
    extern __shared__ char smem[];
    const uint32_t sb = smem_to_u32(smem);
    const int tid = threadIdx.x;
    const int w = tid >> 5, lane = tid & 31;
    const int grp = lane >> 2, qid = lane & 3;

    const int bh = blockIdx.y;
    const int qt = gridDim.x - 1 - blockIdx.x;   // big tiles first
    const int q0 = qt * FBQ;
    const size_t rowbase = (size_t)bh * Sq;

    constexpr uint32_t ONE2 = 0x3C003C00;

    #pragma unroll
    for (int i = 0; i < 4; i++) {
        int idx = tid + i * 256;
        int row = idx >> 3;
        int c = idx & 7;
        cp16(sb + F_Q + row * FROWB + c * 16,
             reinterpret_cast<const char*>(Qh + (rowbase + q0 + row) * Dh) + c * 16);
    }
    CP_COMMIT();

    auto issue_kv = [&](int k0, int stg) {
        const uint32_t base = sb + F_KV + stg * KVSTG;
        #pragma unroll
        for (int i = 0; i < 8; i++) {
            int idx = tid + i * 256;
            int arr = idx >> 10;               // 0=K 1=V
            int row = (idx >> 3) & 127;
            int c = idx & 7;
            const char* src = arr
                ? (const char*)(Vh + (rowbase + k0 + row) * Dh)
                : (const char*)(Kh + (rowbase + k0 + row) * Dh);
            cp16(base + arr * (FCH * FROWB) + row * FROWB + c * 16, src + c * 16);
        }
        CP_COMMIT();
    };

    const int NCH = qt + 1;
    issue_kv(0, 0);

    float m0 = -1e30f, m1 = -1e30f;
    float o[8][4], ls[4];
    #pragma unroll
    for (int t = 0; t < 8; t++)
        #pragma unroll
        for (int i = 0; i < 4; i++) o[t][i] = 0.f;
    #pragma unroll
    for (int i = 0; i < 4; i++) ls[i] = 0.f;

    const int rw0 = q0 + w * 16;
    const uint32_t aOffQ = sb + F_Q + (w * 16 + lane % 16) * FROWB + (lane / 16) * 16;
    const uint32_t bOffK = (((lane >> 4) << 3) + (lane & 7)) * FROWB + ((lane >> 3) & 1) * 16;

    int s = 0;
    for (int ch = 0; ch < NCH; ch++) {
        CP_WAIT0();
        __syncthreads();
        if (ch + 1 < NCH) issue_kv((ch + 1) * FCH, s ^ 1);

        const uint32_t chbase = sb + F_KV + s * KVSTG;

        #pragma unroll
        for (int sub = 0; sub < 2; sub++) {
            const int k0 = ch * FCH + sub * FBK;
            if (k0 > rw0 + 15) continue;

            const uint32_t kbase = chbase + sub * (FBK * FROWB);
            const uint32_t vbase = chbase + FCH * FROWB + sub * (FBK * FROWB);

            float sc[8][4];
            #pragma unroll
            for (int t = 0; t < 8; t++)
                #pragma unroll
                for (int i = 0; i < 4; i++) sc[t][i] = 0.f;

            #pragma unroll
            for (int ks = 0; ks < 4; ks++) {
                uint32_t ah[4];
                ldsm4(ah, aOffQ + ks * 32);
                #pragma unroll
                for (int ntp = 0; ntp < 4; ntp++) {
                    uint32_t bhr[4];
                    ldsm4(bhr, kbase + ntp * 16 * FROWB + bOffK + ks * 32);
                    mma_f16(sc[2 * ntp + 0], ah, bhr[0], bhr[1]);
                    mma_f16(sc[2 * ntp + 1], ah, bhr[2], bhr[3]);
                }
            }

            const bool needMask = (k0 + FBK - 1 > rw0);
            const int r0g = rw0 + grp, r1g = r0g + 8;
            if (needMask) {
                #pragma unroll
                for (int t = 0; t < 8; t++) {
                    const int jc = k0 + t * 8 + qid * 2;
                    if (jc + 0 > r0g) sc[t][0] = -1e4f;
                    if (jc + 1 > r0g) sc[t][1] = -1e4f;
                    if (jc + 0 > r1g) sc[t][2] = -1e4f;
                    if (jc + 1 > r1g) sc[t][3] = -1e4f;
                }
            }

            float mx0 = sc[0][0], mx1 = sc[0][2];
            #pragma unroll
            for (int t = 0; t < 8; t++) {
                mx0 = fmaxf(mx0, fmaxf(sc[t][0], sc[t][1]));
                mx1 = fmaxf(mx1, fmaxf(sc[t][2], sc[t][3]));
            }
            mx0 = fmaxf(mx0, __shfl_xor_sync(0xffffffff, mx0, 1));
            mx0 = fmaxf(mx0, __shfl_xor_sync(0xffffffff, mx0, 2));
            mx1 = fmaxf(mx1, __shfl_xor_sync(0xffffffff, mx1, 1));
            mx1 = fmaxf(mx1, __shfl_xor_sync(0xffffffff, mx1, 2));
            const float nm0 = fmaxf(m0, mx0), nm1 = fmaxf(m1, mx1);
            const float f0 = exp2f(m0 - nm0), f1 = exp2f(m1 - nm1);
            m0 = nm0; m1 = nm1;

            uint32_t pp[8][2];
            #pragma unroll
            for (int t = 0; t < 8; t++) {
                __half2 h01 = __floats2half2_rn(sc[t][0] - nm0, sc[t][1] - nm0);
                __half2 h23 = __floats2half2_rn(sc[t][2] - nm1, sc[t][3] - nm1);
                pp[t][0] = ex2_h2(*reinterpret_cast<uint32_t*>(&h01));
                pp[t][1] = ex2_h2(*reinterpret_cast<uint32_t*>(&h23));
            }

            #pragma unroll
            for (int t = 0; t < 8; t++) {
                o[t][0] *= f0; o[t][1] *= f0; o[t][2] *= f1; o[t][3] *= f1;
            }
            ls[0] *= f0; ls[1] *= f0; ls[2] *= f1; ls[3] *= f1;

            #pragma unroll
            for (int kk = 0; kk < 4; kk++) {
                uint32_t a[4] = { pp[2 * kk][0], pp[2 * kk][1],
                                  pp[2 * kk + 1][0], pp[2 * kk + 1][1] };
                mma_f16(ls, a, ONE2, ONE2);
                #pragma unroll
                for (int ntp = 0; ntp < 4; ntp++) {
                    uint32_t bv[4];
                    ldsm4t(bv, vbase + (kk * 16 + (lane & 15)) * FROWB
                               + (2 * ntp + (lane >> 4)) * 16);
                    mma_f16(o[2 * ntp + 0], a, bv[0], bv[1]);
                    mma_f16(o[2 * ntp + 1], a, bv[2], bv[3]);
                }
            }
        }
        s ^= 1;
    }

    const int b = bh >> 4, h = bh & 15;
    const float inv0 = 1.0f / ls[0], inv1 = 1.0f / ls[2];
    const size_t row0 = ((size_t)b * Sq + (q0 + w * 16 + grp)) * Dm + h * Dh;
    const size_t row1 = row0 + 8 * Dm;
    #pragma unroll
    for (int t = 0; t < 8; t++) {
        const int col = t * 8 + qid * 2;
        *reinterpret_cast<__half2*>(&Oh[row0 + col]) =
            __floats2half2_rn(o[t][0] * inv0, o[t][1] * inv0);
        *reinterpret_cast<__half2*>(&Oh[row1 + col]) =
            __floats2half2_rn(o[t][2] * inv1, o[t][3] * inv1);
    }
}

// ===========================================================================
extern "C" void kernel_launch(void* const* d_in, const int* in_sizes, int n_in,
                              void* d_out, int out_size)
{
    const float* x  = (const float*)d_in[0];
    const float* Wq = (const float*)d_in[2];
    const float* bq = (const float*)d_in[3];
    const float* Wk = (const float*)d_in[4];
    const float* bk = (const float*)d_in[5];
    const float* Wv = (const float*)d_in[6];
    const float* bv = (const float*)d_in[7];
    const float* Wo = (const float*)d_in[8];
    const float* bo = (const float*)d_in[9];
    float* out = (float*)d_out;

    __half *xh, *wptr, *qh, *kh, *vh;
    cudaGetSymbolAddress((void**)&xh, g_xh);
    cudaGetSymbolAddress((void**)&wptr, g_w);
    cudaGetSymbolAddress((void**)&qh, g_Qh);
    cudaGetSymbolAddress((void**)&kh, g_Kh);
    cudaGetSymbolAddress((void**)&vh, g_Vh);

    static bool attr_set = false;
    if (!attr_set) {
        cudaFuncSetAttribute(gemm_qkv, cudaFuncAttributeMaxDynamicSharedMemorySize, GSMEM);
        cudaFuncSetAttribute(gemm_out, cudaFuncAttributeMaxDynamicSharedMemorySize, GSMEM);
        cudaFuncSetAttribute(flash_tc, cudaFuncAttributeMaxDynamicSharedMemorySize, FSMEM);
        attr_set = true;
    }

    const int xn4 = Mr * Dm / 4;                 // 2M float4
    const int wn4 = Dm * Dm / 4;                 // 256K float4
    const size_t wN = (size_t)Dm * Dm;

    // single conversion launch: y=0 -> x, y=1..4 -> weights
    cvt_all<<<dim3((xn4 + 255) / 256, 5), 256>>>(x, Wq, Wk, Wv, Wo, xh, wptr,
                                                 xn4, wn4);

    gemm_qkv<<<dim3(3 * Dm / TBN, Mr / TBM), 256, GSMEM>>>(
        xh, wptr, bq, bk, bv, qh, kh, vh);

    flash_tc<<<dim3(Sq / FBQ, Bz * Hh), 256, FSMEM>>>(qh, kh, vh, xh);

    gemm_out<<<dim3(Dm / TBN, Mr / TBM), 256, GSMEM>>>(xh, wptr + 3 * wN, bo, out);
}

// round 16
// speedup vs baseline: 1.0468x; 1.0228x over previous
#include <cuda_runtime.h>
#include <cuda_fp16.h>
#include <cstdint>
#include <math.h>

// Problem constants
constexpr int Bz = 4;
constexpr int Sq = 2048;
constexpr int Dm = 1024;
constexpr int Hh = 16;
constexpr int Dh = 64;
constexpr int Mr = Bz * Sq;    // 8192

// Scratch (allocation-free rule: __device__ globals)
__device__ __half g_xh[(size_t)Mr * Dm];      // x fp16; later reused for attn-out
__device__ __half g_w[4][(size_t)Dm * Dm];    // Wq, Wk, Wv, Wo fp16 (contiguous)
__device__ __half g_Qh[(size_t)Mr * Dm];
__device__ __half g_Kh[(size_t)Mr * Dm];
__device__ __half g_Vh[(size_t)Mr * Dm];

// ===========================================================================
// PTX helpers
// ===========================================================================
__device__ __forceinline__ uint32_t smem_to_u32(const void* p) {
    uint32_t a;
    asm("{ .reg .u64 t; cvta.to.shared.u64 t, %1; cvt.u32.u64 %0, t; }"
        : "=r"(a) : "l"(p));
    return a;
}
__device__ __forceinline__ void cp16(uint32_t dst, const void* src) {
    asm volatile("cp.async.cg.shared.global [%0], [%1], 16;" :: "r"(dst), "l"(src));
}
#define CP_COMMIT() asm volatile("cp.async.commit_group;" ::: "memory")
#define CP_WAIT1()  asm volatile("cp.async.wait_group 1;" ::: "memory")
#define CP_WAIT0()  asm volatile("cp.async.wait_group 0;" ::: "memory")

__device__ __forceinline__ void ldsm4(uint32_t* r, uint32_t addr) {
    asm volatile("ldmatrix.sync.aligned.m8n8.x4.shared.b16 {%0,%1,%2,%3}, [%4];"
        : "=r"(r[0]), "=r"(r[1]), "=r"(r[2]), "=r"(r[3]) : "r"(addr));
}
__device__ __forceinline__ void ldsm4t(uint32_t* r, uint32_t addr) {
    asm volatile("ldmatrix.sync.aligned.m8n8.x4.trans.shared.b16 {%0,%1,%2,%3}, [%4];"
        : "=r"(r[0]), "=r"(r[1]), "=r"(r[2]), "=r"(r[3]) : "r"(addr));
}
__device__ __forceinline__ void mma_f16(float* d, const uint32_t* a,
                                        uint32_t b0, uint32_t b1) {
    asm volatile(
        "mma.sync.aligned.m16n8k16.row.col.f32.f16.f16.f32 "
        "{%0,%1,%2,%3}, {%4,%5,%6,%7}, {%8,%9}, {%0,%1,%2,%3};"
        : "+f"(d[0]), "+f"(d[1]), "+f"(d[2]), "+f"(d[3])
        : "r"(a[0]), "r"(a[1]), "r"(a[2]), "r"(a[3]), "r"(b0), "r"(b1));
}
__device__ __forceinline__ uint32_t ex2_h2(uint32_t x) {
    uint32_t r;
    asm("ex2.approx.f16x2 %0, %1;" : "=r"(r) : "r"(x));
    return r;
}

// ===========================================================================
// Conversion kernels (pure bandwidth) — R13 configuration
// ===========================================================================
__global__ __launch_bounds__(256)
void cvt_f16(const float* __restrict__ src, __half* __restrict__ dst, int n4)
{
    int i = blockIdx.x * blockDim.x + threadIdx.x;
    if (i >= n4) return;
    float4 v = reinterpret_cast<const float4*>(src)[i];
    reinterpret_cast<__half2*>(dst)[2 * i + 0] = __floats2half2_rn(v.x, v.y);
    reinterpret_cast<__half2*>(dst)[2 * i + 1] = __floats2half2_rn(v.z, v.w);
}

__global__ __launch_bounds__(256)
void cvt_w4(const float* __restrict__ w0, const float* __restrict__ w1,
            const float* __restrict__ w2, const float* __restrict__ w3,
            __half* __restrict__ dst, int n4)
{
    int i = blockIdx.x * blockDim.x + threadIdx.x;
    if (i >= n4) return;
    const float* srcs[4] = {w0, w1, w2, w3};
    const float* src = srcs[blockIdx.y];
    __half* d = dst + (size_t)blockIdx.y * n4 * 4;
    float4 v = reinterpret_cast<const float4*>(src)[i];
    reinterpret_cast<__half2*>(d)[2 * i + 0] = __floats2half2_rn(v.x, v.y);
    reinterpret_cast<__half2*>(d)[2 * i + 1] = __floats2half2_rn(v.z, v.w);
}

// ===========================================================================
// GEMM: 128x128 tiles, k-chunk 64, 8 warps, 2-stage cp.async ring (R13 config)
// ===========================================================================
constexpr int TBM = 128, TBN = 128, TKC = 64;
constexpr int ROWB  = 144;           // 64 fp16 = 128B + 16B pad
constexpr int TILEB = 128 * ROWB;    // 18432
constexpr int GSTG  = 2 * TILEB;     // A+B per stage = 36864
constexpr int GSMEM = 2 * GSTG;      // 73728

__device__ __forceinline__ void gemm_issue(
    const __half* A, const __half* B,
    uint32_t sb, int tid, int bm, int bn, int k0, int stage)
{
    #pragma unroll
    for (int i = 0; i < 8; i++) {
        int idx = tid + i * 256;          // 0..2047
        int tile = idx >> 10;             // 0=A 1=B
        int row  = (idx >> 3) & 127;
        int c16  = idx & 7;
        const __half* src = tile ? B : A;
        int grow = (tile ? bn : bm) + row;
        const char* gsrc = reinterpret_cast<const char*>(src + (size_t)grow * Dm + k0)
                           + c16 * 16;
        uint32_t dst = sb + stage * GSTG + tile * TILEB + row * ROWB + c16 * 16;
        cp16(dst, gsrc);
    }
    CP_COMMIT();
}

__device__ __forceinline__ void gemm_mainloop(
    const __half* A, const __half* B, uint32_t sb, int tid,
    int bm, int bn, int wr, int wc, int lane, float acc[2][8][4])
{
    const uint32_t aOff = (lane % 16) * ROWB + (lane / 16) * 16;
    const uint32_t bOff = (((lane >> 4) << 3) + (lane & 7)) * ROWB + ((lane >> 3) & 1) * 16;

    gemm_issue(A, B, sb, tid, bm, bn, 0, 0);

    const int NCK = Dm / TKC;    // 16
    int s = 0;
    for (int ck = 0; ck < NCK; ck++) {
        CP_WAIT0();
        __syncthreads();
        if (ck + 1 < NCK)
            gemm_issue(A, B, sb, tid, bm, bn, (ck + 1) * TKC, s ^ 1);

        const uint32_t stg = sb + s * GSTG;
        const uint32_t aB  = stg + (wr * 32) * ROWB + aOff;
        const uint32_t bB  = stg + TILEB + (wc * 64) * ROWB + bOff;

        #pragma unroll
        for (int ks = 0; ks < 4; ks++) {
            uint32_t ah[2][4];
            #pragma unroll
            for (int mt = 0; mt < 2; mt++)
                ldsm4(ah[mt], aB + mt * 16 * ROWB + ks * 32);
            #pragma unroll
            for (int nt = 0; nt < 4; nt++) {
                uint32_t bh[4];
                ldsm4(bh, bB + nt * 16 * ROWB + ks * 32);
                #pragma unroll
                for (int mt = 0; mt < 2; mt++) {
                    mma_f16(acc[mt][2 * nt + 0], ah[mt], bh[0], bh[1]);
                    mma_f16(acc[mt][2 * nt + 1], ah[mt], bh[2], bh[3]);
                }
            }
        }
        s ^= 1;
    }
}

// ---------------------------------------------------------------------------
// Fused QKV projection: B = packed [Wq;Wk;Wv]. fp16 scatter.
// Q outputs pre-scaled by (1/sqrt(Dh))*log2(e) for the flash exp2 domain.
// ---------------------------------------------------------------------------
constexpr float QSCALE = 0.18033688011112042f;  // (1/8) * log2(e)

__global__ __launch_bounds__(256, 2)
void gemm_qkv(const __half* __restrict__ A, const __half* __restrict__ Bw,
              const float* __restrict__ bq, const float* __restrict__ bk,
              const float* __restrict__ bv,
              __half* __restrict__ Qh, __half* __restrict__ Kh,
              __half* __restrict__ Vh)
{
    extern __shared__ char smem[];
    const uint32_t sb = smem_to_u32(smem);
    const int tid = threadIdx.x;
    const int wid = tid >> 5, lane = tid & 31;
    const int bm = blockIdx.y * TBM, bn = blockIdx.x * TBN;   // bn in [0,3072)
    const int wr = wid & 3, wc = wid >> 2;

    float acc[2][8][4];
    #pragma unroll
    for (int a = 0; a < 2; a++)
        #pragma unroll
        for (int b = 0; b < 8; b++)
            #pragma unroll
            for (int c = 0; c < 4; c++) acc[a][b][c] = 0.f;

    gemm_mainloop(A, Bw, sb, tid, bm, bn, wr, wc, lane, acc);

    const int sel = bn >> 10;
    const int bnl = bn & 1023;
    const float* bias = (sel == 0) ? bq : (sel == 1) ? bk : bv;
    __half* dst = (sel == 0) ? Qh : (sel == 1) ? Kh : Vh;
    const float osc = (sel == 0) ? QSCALE : 1.0f;

    const int grp = lane >> 2, qid = lane & 3;
    #pragma unroll
    for (int mt = 0; mt < 2; mt++) {
        #pragma unroll
        for (int na = 0; na < 8; na++) {
            const int n0 = bnl + wc * 64 + na * 8 + qid * 2;
            const float b0 = bias[n0], b1 = bias[n0 + 1];
            #pragma unroll
            for (int half = 0; half < 2; half++) {
                const int m = bm + wr * 32 + mt * 16 + grp + half * 8;
                const float v0 = (acc[mt][na][2 * half + 0] + b0) * osc;
                const float v1 = (acc[mt][na][2 * half + 1] + b1) * osc;
                const int b = m >> 11;
                const int sI = m & 2047;
                const int h = n0 >> 6;
                const int d = n0 & 63;
                const size_t o = ((((size_t)b * Hh + h) * Sq + sI) << 6) + d;
                *reinterpret_cast<__half2*>(&dst[o]) = __floats2half2_rn(v0, v1);
            }
        }
    }
}

// ---------------------------------------------------------------------------
// Output projection: fp32 row-major out
// ---------------------------------------------------------------------------
__global__ __launch_bounds__(256, 2)
void gemm_out(const __half* __restrict__ A, const __half* __restrict__ Bw,
              const float* __restrict__ bias, float* __restrict__ C)
{
    extern __shared__ char smem[];
    const uint32_t sb = smem_to_u32(smem);
    const int tid = threadIdx.x;
    const int wid = tid >> 5, lane = tid & 31;
    const int bm = blockIdx.y * TBM, bn = blockIdx.x * TBN;
    const int wr = wid & 3, wc = wid >> 2;

    float acc[2][8][4];
    #pragma unroll
    for (int a = 0; a < 2; a++)
        #pragma unroll
        for (int b = 0; b < 8; b++)
            #pragma unroll
            for (int c = 0; c < 4; c++) acc[a][b][c] = 0.f;

    gemm_mainloop(A, Bw, sb, tid, bm, bn, wr, wc, lane, acc);

    const int grp = lane >> 2, qid = lane & 3;
    #pragma unroll
    for (int mt = 0; mt < 2; mt++) {
        #pragma unroll
        for (int na = 0; na < 8; na++) {
            const int n0 = bn + wc * 64 + na * 8 + qid * 2;
            const float b0 = bias[n0], b1 = bias[n0 + 1];
            #pragma unroll
            for (int half = 0; half < 2; half++) {
                const int m = bm + wr * 32 + mt * 16 + grp + half * 8;
                *reinterpret_cast<float2*>(&C[(size_t)m * Dm + n0]) =
                    make_float2(acc[mt][na][2 * half + 0] + b0,
                                acc[mt][na][2 * half + 1] + b1);
            }
        }
    }
}

// ===========================================================================
// Tensor-core flash attention (R13 config — best measured).
// FBQ=128, 8 warps, 2 CTA/SM, 128-key chunks (2 subtiles per sync),
// 2-stage ring, f16x2 exp, row sums via MMA-with-ones, Q pre-scaled.
// Output fp16 row-major [b*s, Dm].
// ===========================================================================
constexpr int FBQ = 128, FBK = 64, FCH = 128;
constexpr int FROWB = 144;
constexpr int F_Q   = 0;
constexpr int F_KV  = FBQ * FROWB;
constexpr int KVSTG = 2 * FCH * FROWB;          // 36864
constexpr int FSMEM = F_KV + 2 * KVSTG;         // 92160

__global__ __launch_bounds__(256, 2)
void flash_tc(const __half* __restrict__ Qh, const __half* __restrict__ Kh,
              const __half* __restrict__ Vh, __half* __restrict__ Oh)
{
    extern __shared__ char smem[];
    const uint32_t sb = smem_to_u32(smem);
    const int tid = threadIdx.x;
    const int w = tid >> 5, lane = tid & 31;
    const int grp = lane >> 2, qid = lane & 3;

    const int bh = blockIdx.y;
    const int qt = gridDim.x - 1 - blockIdx.x;   // big tiles first
    const int q0 = qt * FBQ;
    const size_t rowbase = (size_t)bh * Sq;

    constexpr uint32_t ONE2 = 0x3C003C00;

    #pragma unroll
    for (int i = 0; i < 4; i++) {
        int idx = tid + i * 256;
        int row = idx >> 3;
        int c = idx & 7;
        cp16(sb + F_Q + row * FROWB + c * 16,
             reinterpret_cast<const char*>(Qh + (rowbase + q0 + row) * Dh) + c * 16);
    }
    CP_COMMIT();

    auto issue_kv = [&](int k0, int stg) {
        const uint32_t base = sb + F_KV + stg * KVSTG;
        #pragma unroll
        for (int i = 0; i < 8; i++) {
            int idx = tid + i * 256;
            int arr = idx >> 10;               // 0=K 1=V
            int row = (idx >> 3) & 127;
            int c = idx & 7;
            const char* src = arr
                ? (const char*)(Vh + (rowbase + k0 + row) * Dh)
                : (const char*)(Kh + (rowbase + k0 + row) * Dh);
            cp16(base + arr * (FCH * FROWB) + row * FROWB + c * 16, src + c * 16);
        }
        CP_COMMIT();
    };

    const int NCH = qt + 1;
    issue_kv(0, 0);

    float m0 = -1e30f, m1 = -1e30f;
    float o[8][4], ls[4];
    #pragma unroll
    for (int t = 0; t < 8; t++)
        #pragma unroll
        for (int i = 0; i < 4; i++) o[t][i] = 0.f;
    #pragma unroll
    for (int i = 0; i < 4; i++) ls[i] = 0.f;

    const int rw0 = q0 + w * 16;
    const uint32_t aOffQ = sb + F_Q + (w * 16 + lane % 16) * FROWB + (lane / 16) * 16;
    const uint32_t bOffK = (((lane >> 4) << 3) + (lane & 7)) * FROWB + ((lane >> 3) & 1) * 16;

    int s = 0;
    for (int ch = 0; ch < NCH; ch++) {
        CP_WAIT0();
        __syncthreads();
        if (ch + 1 < NCH) issue_kv((ch + 1) * FCH, s ^ 1);

        const uint32_t chbase = sb + F_KV + s * KVSTG;

        #pragma unroll
        for (int sub = 0; sub < 2; sub++) {
            const int k0 = ch * FCH + sub * FBK;
            if (k0 > rw0 + 15) continue;

            const uint32_t kbase = chbase + sub * (FBK * FROWB);
            const uint32_t vbase = chbase + FCH * FROWB + sub * (FBK * FROWB);

            float sc[8][4];
            #pragma unroll
            for (int t = 0; t < 8; t++)
                #pragma unroll
                for (int i = 0; i < 4; i++) sc[t][i] = 0.f;

            #pragma unroll
            for (int ks = 0; ks < 4; ks++) {
                uint32_t ah[4];
                ldsm4(ah, aOffQ + ks * 32);
                #pragma unroll
                for (int ntp = 0; ntp < 4; ntp++) {
                    uint32_t bhr[4];
                    ldsm4(bhr, kbase + ntp * 16 * FROWB + bOffK + ks * 32);
                    mma_f16(sc[2 * ntp + 0], ah, bhr[0], bhr[1]);
                    mma_f16(sc[2 * ntp + 1], ah, bhr[2], bhr[3]);
                }
            }

            const bool needMask = (k0 + FBK - 1 > rw0);
            const int r0g = rw0 + grp, r1g = r0g + 8;
            if (needMask) {
                #pragma unroll
                for (int t = 0; t < 8; t++) {
                    const int jc = k0 + t * 8 + qid * 2;
                    if (jc + 0 > r0g) sc[t][0] = -1e4f;
                    if (jc + 1 > r0g) sc[t][1] = -1e4f;
                    if (jc + 0 > r1g) sc[t][2] = -1e4f;
                    if (jc + 1 > r1g) sc[t][3] = -1e4f;
                }
            }

            float mx0 = sc[0][0], mx1 = sc[0][2];
            #pragma unroll
            for (int t = 0; t < 8; t++) {
                mx0 = fmaxf(mx0, fmaxf(sc[t][0], sc[t][1]));
                mx1 = fmaxf(mx1, fmaxf(sc[t][2], sc[t][3]));
            }
            mx0 = fmaxf(mx0, __shfl_xor_sync(0xffffffff, mx0, 1));
            mx0 = fmaxf(mx0, __shfl_xor_sync(0xffffffff, mx0, 2));
            mx1 = fmaxf(mx1, __shfl_xor_sync(0xffffffff, mx1, 1));
            mx1 = fmaxf(mx1, __shfl_xor_sync(0xffffffff, mx1, 2));
            const float nm0 = fmaxf(m0, mx0), nm1 = fmaxf(m1, mx1);
            const float f0 = exp2f(m0 - nm0), f1 = exp2f(m1 - nm1);
            m0 = nm0; m1 = nm1;

            uint32_t pp[8][2];
            #pragma unroll
            for (int t = 0; t < 8; t++) {
                __half2 h01 = __floats2half2_rn(sc[t][0] - nm0, sc[t][1] - nm0);
                __half2 h23 = __floats2half2_rn(sc[t][2] - nm1, sc[t][3] - nm1);
                pp[t][0] = ex2_h2(*reinterpret_cast<uint32_t*>(&h01));
                pp[t][1] = ex2_h2(*reinterpret_cast<uint32_t*>(&h23));
            }

            #pragma unroll
            for (int t = 0; t < 8; t++) {
                o[t][0] *= f0; o[t][1] *= f0; o[t][2] *= f1; o[t][3] *= f1;
            }
            ls[0] *= f0; ls[1] *= f0; ls[2] *= f1; ls[3] *= f1;

            #pragma unroll
            for (int kk = 0; kk < 4; kk++) {
                uint32_t a[4] = { pp[2 * kk][0], pp[2 * kk][1],
                                  pp[2 * kk + 1][0], pp[2 * kk + 1][1] };
                mma_f16(ls, a, ONE2, ONE2);
                #pragma unroll
                for (int ntp = 0; ntp < 4; ntp++) {
                    uint32_t bv[4];
                    ldsm4t(bv, vbase + (kk * 16 + (lane & 15)) * FROWB
                               + (2 * ntp + (lane >> 4)) * 16);
                    mma_f16(o[2 * ntp + 0], a, bv[0], bv[1]);
                    mma_f16(o[2 * ntp + 1], a, bv[2], bv[3]);
                }
            }
        }
        s ^= 1;
    }

    const int b = bh >> 4, h = bh & 15;
    const float inv0 = 1.0f / ls[0], inv1 = 1.0f / ls[2];
    const size_t row0 = ((size_t)b * Sq + (q0 + w * 16 + grp)) * Dm + h * Dh;
    const size_t row1 = row0 + 8 * Dm;
    #pragma unroll
    for (int t = 0; t < 8; t++) {
        const int col = t * 8 + qid * 2;
        *reinterpret_cast<__half2*>(&Oh[row0 + col]) =
            __floats2half2_rn(o[t][0] * inv0, o[t][1] * inv0);
        *reinterpret_cast<__half2*>(&Oh[row1 + col]) =
            __floats2half2_rn(o[t][2] * inv1, o[t][3] * inv1);
    }
}

// ===========================================================================
extern "C" void kernel_launch(void* const* d_in, const int* in_sizes, int n_in,
                              void* d_out, int out_size)
{
    const float* x  = (const float*)d_in[0];
    const float* Wq = (const float*)d_in[2];
    const float* bq = (const float*)d_in[3];
    const float* Wk = (const float*)d_in[4];
    const float* bk = (const float*)d_in[5];
    const float* Wv = (const float*)d_in[6];
    const float* bv = (const float*)d_in[7];
    const float* Wo = (const float*)d_in[8];
    const float* bo = (const float*)d_in[9];
    float* out = (float*)d_out;

    __half *xh, *wptr, *qh, *kh, *vh;
    cudaGetSymbolAddress((void**)&xh, g_xh);
    cudaGetSymbolAddress((void**)&wptr, g_w);
    cudaGetSymbolAddress((void**)&qh, g_Qh);
    cudaGetSymbolAddress((void**)&kh, g_Kh);
    cudaGetSymbolAddress((void**)&vh, g_Vh);

    static bool attr_set = false;
    if (!attr_set) {
        cudaFuncSetAttribute(gemm_qkv, cudaFuncAttributeMaxDynamicSharedMemorySize, GSMEM);
        cudaFuncSetAttribute(gemm_out, cudaFuncAttributeMaxDynamicSharedMemorySize, GSMEM);
        cudaFuncSetAttribute(flash_tc, cudaFuncAttributeMaxDynamicSharedMemorySize, FSMEM);
        attr_set = true;
    }

    const size_t wN = (size_t)Dm * Dm;
    const int xn4 = Mr * Dm / 4;
    const int wn4 = (int)(wN / 4);

    cvt_f16<<<(xn4 + 255) / 256, 256>>>(x, xh, xn4);
    cvt_w4<<<dim3((wn4 + 255) / 256, 4), 256>>>(Wq, Wk, Wv, Wo, wptr, wn4);

    gemm_qkv<<<dim3(3 * Dm / TBN, Mr / TBM), 256, GSMEM>>>(
        xh, wptr, bq, bk, bv, qh, kh, vh);

    flash_tc<<<dim3(Sq / FBQ, Bz * Hh), 256, FSMEM>>>(qh, kh, vh, xh);

    gemm_out<<<dim3(Dm / TBN, Mr / TBM), 256, GSMEM>>>(xh, wptr + 3 * wN, bo, out);
}